// round 16
// baseline (speedup 1.0000x reference)
#include <cuda_runtime.h>
#include <cstdint>
#include <cstddef>

#define B_TOT 512
#define S_LEN 256
#define T_TAG 128
#define X_PAD (T_TAG + 2)
#define NB 4
#define NCTA (B_TOT / NB)      // 128 CTAs, 1 per SM, 512 threads
#define NTHREADS 512
#define HALF 128               // meet-in-the-middle step count
#define LN2 0.6931471805599453f

__device__ float g_partial[NCTA];
__device__ int g_count = 0;

__device__ __forceinline__ float warp_sum(float v) {
#pragma unroll
    for (int o = 16; o > 0; o >>= 1)
        v += __shfl_xor_sync(0xffffffffu, v, o);
    return v;
}
__device__ __forceinline__ unsigned long long pack2(float lo, float hi) {
    unsigned long long r;
    asm("mov.b64 %0, {%1, %2};" : "=l"(r) : "f"(lo), "f"(hi));
    return r;
}
__device__ __forceinline__ void fma2(unsigned long long& acc, unsigned long long a,
                                     unsigned long long b) {
    asm("fma.rn.f32x2 %0, %1, %2, %0;" : "+l"(acc) : "l"(a), "l"(b));
}
__device__ __forceinline__ unsigned long long add2(unsigned long long a,
                                                   unsigned long long b) {
    unsigned long long r;
    asm("add.rn.f32x2 %0, %1, %2;" : "=l"(r) : "l"(a), "l"(b));
    return r;
}
__device__ __forceinline__ void unpack2(unsigned long long v, float& lo, float& hi) {
    asm("mov.b64 {%0, %1}, %2;" : "=f"(lo), "=f"(hi) : "l"(v));
}

__global__ __launch_bounds__(NTHREADS, 1) void crf_main(
    const float* __restrict__ emis,
    const void* __restrict__ tags_raw,
    const void* __restrict__ mask_raw,
    const float* __restrict__ trans,
    float* __restrict__ out)
{
    // plane[0] = alpha (fwd, emission folded in), plane[1] = u = gamma*d (bwd)
    __shared__ __align__(16) float plane[2][NB][T_TAG];
    __shared__ __align__(16) float2 xch[2][NB][4][X_PAD];  // [vec][batch][chunk-pair][col]
    __shared__ float red_sh[16];
    __shared__ float scr[NB];
    __shared__ float gred[16];
    __shared__ unsigned char msk[NB][S_LEN];
    __shared__ int is_last;

    const int tid  = threadIdx.x;
    const int lane = tid & 31;
    const int wid  = tid >> 5;
    // dot role: vec 0 = forward (warps 0-7), vec 1 = backward (warps 8-15)
    const int vec  = wid >> 3;
    const int w8   = wid & 7;
    const int i0   = w8 * 16;          // my 16 reduction-indices
    const int cp   = w8 >> 1;          // chunk pair
    const int par  = w8 & 1;           // float2 component
    // reduce role: batch b, column c (owns both alpha(b,c) and gamma(b,c))
    const int b    = tid >> 7;
    const int c    = tid & 127;
    const int b0   = blockIdx.x * NB;

    // ---- dtype probes (input-derived, deterministic) ----
    const int* t32 = (const int*)tags_raw;
    const int tags_is_i32 = __syncthreads_or(t32[2 * tid + 1] != 0);
    const int* m32 = (const int*)mask_raw;
    const unsigned char* m8 = (const unsigned char*)mask_raw;
    const bool mask_is_u8 = (m32[0] == 0x01010101);

#define MASK_AT(idx) (mask_is_u8 ? (m8[idx] != 0) : (m32[idx] != 0))
#define TAG_AT(idx)  (tags_is_i32 ? t32[idx] : t32[2 * (idx)])

    // ---- E (fwd warps) or E^T (bwd warps), packed along reduction index ----
    unsigned long long E2[8][4];
#pragma unroll
    for (int ip = 0; ip < 8; ip++) {
#pragma unroll
        for (int cc = 0; cc < 4; cc++) {
            const int col = lane + 32 * cc;   // fwd: output col; bwd: output row
            float lo, hi;
            if (vec == 0) {   // E[i][col], i = i0+2ip, i0+2ip+1
                lo = trans[(i0 + 2 * ip)     * T_TAG + col];
                hi = trans[(i0 + 2 * ip + 1) * T_TAG + col];
            } else {          // E[col][j], j = i0+2ip, i0+2ip+1  (row dot)
                lo = trans[col * T_TAG + (i0 + 2 * ip)];
                hi = trans[col * T_TAG + (i0 + 2 * ip + 1)];
            }
            E2[ip][cc] = pack2(__expf(lo), __expf(hi));
        }
    }

    // ---- mask preload ----
    for (int idx = tid; idx < NB * S_LEN; idx += NTHREADS) {
        int nb = idx >> 8, tt = idx & 255;
        msk[nb][tt] = MASK_AT((unsigned)(b0 + nb) * S_LEN + tt) ? 1 : 0;
    }

    const unsigned ebm = (unsigned)(b0 + b) * (S_LEN * T_TAG);

    // ---- init: alpha_0 = exp(emit_0); gamma_255 = 1; u_255 = exp(emit_255) ----
    float v = __expf(emis[ebm + c]);
    float g = 1.f;
    float lsumF = 0.f, lsumB = 0.f, pend = 0.f;
    plane[0][b][c] = v;
    plane[1][b][c] = __expf(emis[ebm + 255u * T_TAG + c]);
    __syncthreads();   // covers planes, msk, probes

    // prefetch iter 0
    float ex_f = __expf(emis[ebm + 1u * T_TAG + c]);      // d_1
    float ex_b = __expf(emis[ebm + 254u * T_TAG + c]);    // d_254 (next bwd store)
    bool  k_f  = msk[b][1] != 0;
    bool  k_b  = msk[b][255] != 0;

    // ---- meet-in-the-middle recursion: 128 coupled steps ----
#pragma unroll 2
    for (int n = 0; n < HALF; n++) {
        const bool resc = (n & 3) == 3;
        float sF = 1.f, lgF = 0.f, sG = 1.f, lgG = 0.f;
        if (resc) {   // sample col 1 (col 0 is the pad tag: value 0)
            const float a1 = plane[0][b][1];
            const float u1 = plane[1][b][1];
            sF = __fdividef(1.f, a1); lgF = __log2f(a1);
            sG = __fdividef(1.f, u1); lgG = __log2f(u1);
        }

        // prefetch next iter (overrun reads stay in-bounds and are unused)
        float exNf = __expf(emis[ebm + (unsigned)(n + 2) * T_TAG + c]);
        float exNb = __expf(emis[ebm + (unsigned)(253 - n) * T_TAG + c]);
        bool  kNf  = msk[b][n + 2] != 0;
        bool  kNb  = (n <= 125) && (msk[b][254 - n] != 0);

        // ---- dot: my vec, my 16 indices, 4 batches (2 at a time for regs) ----
#pragma unroll
        for (int bg = 0; bg < 2; bg++) {
            unsigned long long acc[2][4];
#pragma unroll
            for (int bi = 0; bi < 2; bi++)
#pragma unroll
                for (int cc = 0; cc < 4; cc++) acc[bi][cc] = 0ull;
#pragma unroll
            for (int q = 0; q < 4; q++) {
#pragma unroll
                for (int bi = 0; bi < 2; bi++) {
                    ulonglong2 pv =
                        *(const ulonglong2*)&plane[vec][2 * bg + bi][i0 + 4 * q];
#pragma unroll
                    for (int cc = 0; cc < 4; cc++) {
                        fma2(acc[bi][cc], E2[2 * q][cc],     pv.x);
                        fma2(acc[bi][cc], E2[2 * q + 1][cc], pv.y);
                    }
                }
            }
#pragma unroll
            for (int bi = 0; bi < 2; bi++)
#pragma unroll
                for (int cc = 0; cc < 4; cc++) {
                    float lo, hi;
                    unpack2(acc[bi][cc], lo, hi);
                    ((float*)&xch[vec][2 * bg + bi][cp][lane + 32 * cc])[par] = lo + hi;
                }
        }
        __syncthreads();   // BAR1: partials visible

        // ---- reduce both vectors for my (batch, col) ----
        const unsigned long long* xa = (const unsigned long long*)&xch[0][b][0][c];
        unsigned long long a0 = add2(xa[0],         xa[X_PAD]);
        unsigned long long a1 = add2(xa[2 * X_PAD], xa[3 * X_PAD]);
        float al, ah;
        unpack2(add2(a0, a1), al, ah);
        const float X_a = al + ah;

        const unsigned long long* xg = (const unsigned long long*)&xch[1][b][0][c];
        unsigned long long g0 = add2(xg[0],         xg[X_PAD]);
        unsigned long long g1 = add2(xg[2 * X_PAD], xg[3 * X_PAD]);
        float gl, gh;
        unpack2(add2(g0, g1), gl, gh);
        const float X_g = gl + gh;

        // forward update (scale applied at consume)
        if (k_f) { v = X_a * (ex_f * (resc ? sF : 1.f)); lsumF += resc ? lgF : 0.f; }
        // backward update (scale applied at store last iter; log shifted via pend)
        if (k_b) { g = X_g; lsumB += pend; }
        pend = resc ? lgG : 0.f;

        plane[0][b][c] = v;
        plane[1][b][c] = g * (ex_b * (resc ? sG : 1.f));

        ex_f = exNf; ex_b = exNb; k_f = kNf; k_b = kNb;
        __syncthreads();   // BAR2: planes visible to dot warps
    }

    // ---- merge: Z = sum_c alpha_128[c] * gamma_128[c], scales in lsumF+lsumB ----
    {
        float term = warp_sum(v * g);
        if (lane == 0) red_sh[wid] = term;
    }
    __syncthreads();
    if (c == 0) {   // tid = 128*b (lane 0 of warp 4b)
        const int rb = b * 4;
        const float tot = red_sh[rb] + red_sh[rb + 1] + red_sh[rb + 2] + red_sh[rb + 3];
        scr[b] = (__log2f(tot) + lsumF + lsumB) * LN2;
    }

    // ---- gold: batch b, 128 threads each ----
    {
        const unsigned tb  = (unsigned)(b0 + b) * S_LEN;
        const unsigned ebn = tb * T_TAG;
        float gg = 0.f;
        for (int tt = c; tt < S_LEN; tt += 128) {
            int tg = TAG_AT(tb + tt);
            bool mk = msk[b][tt] != 0;
            if (mk) gg += emis[ebn + (unsigned)tt * T_TAG + tg];
            if (tt + 1 < S_LEN) {
                if (mk && msk[b][tt + 1]) gg += trans[tg * T_TAG + TAG_AT(tb + tt + 1)];
            }
        }
        gg = warp_sum(gg);
        if (lane == 0) gred[wid] = gg;
    }
    __syncthreads();   // scr + gred visible

    if (tid == 0) {
        float part = 0.f;
#pragma unroll
        for (int nb = 0; nb < NB; nb++)
            part += scr[nb] - (gred[4 * nb] + gred[4 * nb + 1] +
                               gred[4 * nb + 2] + gred[4 * nb + 3]);
        g_partial[blockIdx.x] = part;
        __threadfence();
        int old = atomicAdd(&g_count, 1);
        is_last = (old == NCTA - 1) ? 1 : 0;
    }
    __syncthreads();

    if (is_last) {
        __threadfence();
        float vv = (tid < NCTA) ? __ldcg(&g_partial[tid]) : 0.f;
        vv = warp_sum(vv);
        if (lane == 0) gred[wid] = vv;
        __syncthreads();
        if (tid == 0) {
            float tot = 0.f;
#pragma unroll
            for (int w = 0; w < 16; w++) tot += gred[w];
            out[0] = tot * (1.0f / (float)B_TOT);
            g_count = 0;   // reset for next graph replay
        }
    }
#undef MASK_AT
#undef TAG_AT
}

extern "C" void kernel_launch(void* const* d_in, const int* in_sizes, int n_in,
                              void* d_out, int out_size) {
    const float* emis  = (const float*)d_in[0];
    const void*  tags  = d_in[1];
    const void*  mask  = d_in[2];
    const float* trans = (const float*)d_in[3];
    float* out = (float*)d_out;

    crf_main<<<NCTA, NTHREADS>>>(emis, tags, mask, trans, out);
}

// round 17
// speedup vs baseline: 1.6576x; 1.6576x over previous
#include <cuda_runtime.h>
#include <cuda_bf16.h>
#include <cstdint>
#include <cstddef>

#define B_TOT 512
#define S_LEN 256
#define T_TAG 128
#define NB 2
#define NCTA (B_TOT / NB)      // 256 CTAs, 2 per SM
#define NTHREADS 256
#define LN2 0.6931471805599453f

__device__ float g_partial[NCTA];
__device__ int g_count = 0;

__device__ __forceinline__ float warp_sum(float v) {
#pragma unroll
    for (int o = 16; o > 0; o >>= 1)
        v += __shfl_xor_sync(0xffffffffu, v, o);
    return v;
}

__global__ __launch_bounds__(NTHREADS, 2) void crf_main(
    const float* __restrict__ emis,
    const void* __restrict__ tags_raw,
    const void* __restrict__ mask_raw,
    const float* __restrict__ trans,
    float* __restrict__ out)
{
    __shared__ __align__(16) __nv_bfloat16 p_lin[NB][T_TAG];  // v (linear), bf16
    __shared__ __align__(16) float xch[NB][8][T_TAG];         // [batch][chunk][col]
    __shared__ float red_sh[8];
    __shared__ float scr[NB];
    __shared__ float gred[8];
    __shared__ unsigned char msk[NB][S_LEN];
    __shared__ int is_last;

    const int tid  = threadIdx.x;
    const int lane = tid & 31;
    const int wid  = tid >> 5;
    // dot role: warp covers i in [16w,16w+16); lanes 0-15 batch 0, 16-31 batch 1;
    // lane covers 8 cols: 4*lr+k (k<4) and 64+4*lr+k-4 (k>=4)
    const int lr   = lane & 15;
    const int bd   = lane >> 4;
    const int i0   = wid * 16;
    // reduce role: batch bb, column c
    const int bb   = tid >> 7;
    const int c    = tid & 127;
    const int b0   = blockIdx.x * NB;

    // ---- dtype probes (input-derived, deterministic) ----
    const int* t32 = (const int*)tags_raw;
    const int tags_is_i32 = __syncthreads_or(t32[2 * tid + 1] != 0);
    const int* m32 = (const int*)mask_raw;
    const unsigned char* m8 = (const unsigned char*)mask_raw;
    const bool mask_is_u8 = (m32[0] == 0x01010101);

#define MASK_AT(idx) (mask_is_u8 ? (m8[idx] != 0) : (m32[idx] != 0))
#define TAG_AT(idx)  (tags_is_i32 ? t32[idx] : t32[2 * (idx)])

    // ---- E in bf16x2, packed along i: E2[ip][k] = (E[i0+2ip,col], E[i0+2ip+1,col]) ----
    __nv_bfloat162 E2[8][8];
#pragma unroll
    for (int ip = 0; ip < 8; ip++) {
#pragma unroll
        for (int kk = 0; kk < 8; kk++) {
            const int col = (kk < 4) ? (4 * lr + kk) : (64 + 4 * lr + kk - 4);
            float elo = __expf(trans[(i0 + 2 * ip)     * T_TAG + col]);
            float ehi = __expf(trans[(i0 + 2 * ip + 1) * T_TAG + col]);
            E2[ip][kk] = __floats2bfloat162_rn(elo, ehi);
        }
    }

    // ---- mask preload ----
    for (int idx = tid; idx < NB * S_LEN; idx += NTHREADS) {
        int nb = idx >> 8, tt = idx & 255;
        msk[nb][tt] = MASK_AT((unsigned)(b0 + nb) * S_LEN + tt) ? 1 : 0;
    }

    // 32-bit offsets: max index 2^24 < 2^31
    const unsigned eb = (unsigned)(b0 + bb) * (S_LEN * T_TAG);

    // ---- v0 = exp(em0), lsum = 0 ----
    float v = __expf(emis[eb + c]);
    float lsum = 0.f;
    p_lin[bb][c] = __float2bfloat16(v);
    __syncthreads();   // covers p_lin, msk, probes

    // prefetch t=1
    float ex = __expf(emis[eb + T_TAG + c]);
    bool  k  = msk[bb][1] != 0;

    // ---- forward recursion (linear domain, v[1]-sampled rescale every 4th step) ----
#pragma unroll 2
    for (int t = 1; t < S_LEN; t++) {
        const bool resc = (t & 3) == 0;
        float s = 1.f, lg = 0.f;
        if (resc) {
            // any positive per-batch scalar works exactly; sample column 1
            // (column 0 is the pad tag: E col 0 == 0, so v[0] == 0 after step 1)
            const float v1 = __bfloat162float(p_lin[bb][1]);
            s  = __fdividef(1.f, v1);
            lg = __log2f(v1);
        }
        const float ems = resc ? ex * s : ex;

        // prefetch t+1
        float exN = 0.f;
        bool  kN = false;
        if (t + 1 < S_LEN) {
            exN = __expf(emis[eb + (unsigned)(t + 1) * T_TAG + c]);
            kN = msk[bb][t + 1] != 0;
        }

        // ---- dot: my 16 i's, my batch (bd), 8 cols, bf16 HFMA2 ----
        // p loads: 16 bf16 = 32B = 2x LDS.128 broadcast per half-warp
        uint4 pa = *(const uint4*)&p_lin[bd][i0];
        uint4 pb = *(const uint4*)&p_lin[bd][i0 + 8];
        __nv_bfloat162 pv[8];
        pv[0] = *(__nv_bfloat162*)&pa.x; pv[1] = *(__nv_bfloat162*)&pa.y;
        pv[2] = *(__nv_bfloat162*)&pa.z; pv[3] = *(__nv_bfloat162*)&pa.w;
        pv[4] = *(__nv_bfloat162*)&pb.x; pv[5] = *(__nv_bfloat162*)&pb.y;
        pv[6] = *(__nv_bfloat162*)&pb.z; pv[7] = *(__nv_bfloat162*)&pb.w;

        __nv_bfloat162 acc[8];
        const __nv_bfloat162 z2 = __floats2bfloat162_rn(0.f, 0.f);
#pragma unroll
        for (int kk = 0; kk < 8; kk++) acc[kk] = z2;
#pragma unroll
        for (int ip = 0; ip < 8; ip++) {
#pragma unroll
            for (int kk = 0; kk < 8; kk++)
                acc[kk] = __hfma2(E2[ip][kk], pv[ip], acc[kk]);
        }
        // fold even/odd i to f32 and store: 2 conflict-free STS.128
        {
            float4 f1, f2;
            f1.x = __low2float(acc[0]) + __high2float(acc[0]);
            f1.y = __low2float(acc[1]) + __high2float(acc[1]);
            f1.z = __low2float(acc[2]) + __high2float(acc[2]);
            f1.w = __low2float(acc[3]) + __high2float(acc[3]);
            f2.x = __low2float(acc[4]) + __high2float(acc[4]);
            f2.y = __low2float(acc[5]) + __high2float(acc[5]);
            f2.z = __low2float(acc[6]) + __high2float(acc[6]);
            f2.w = __low2float(acc[7]) + __high2float(acc[7]);
            *(float4*)&xch[bd][wid][4 * lr]      = f1;
            *(float4*)&xch[bd][wid][64 + 4 * lr] = f2;
        }
        __syncthreads();   // BAR1: partials visible

        // ---- reduce 8 chunk partials for my (batch, col) ----
        const float* xp = &xch[bb][0][c];
        const float X = ((xp[0]          + xp[T_TAG])     + (xp[2 * T_TAG] + xp[3 * T_TAG]))
                      + ((xp[4 * T_TAG] + xp[5 * T_TAG]) + (xp[6 * T_TAG] + xp[7 * T_TAG]));

        if (k) { v = X * ems; lsum += resc ? lg : 0.f; }
        p_lin[bb][c] = __float2bfloat16(v);

        ex = exN; k = kN;
        __syncthreads();   // BAR2: p visible to all dot warps
    }

    // ---- log_Z: ln Z = (log2(sum v) + lsum) * ln2 ----
    float su = warp_sum(v);
    if (lane == 0) red_sh[wid] = su;
    __syncthreads();
    if (c == 0) {   // tid 0 and 128
        const int rbase = bb * 4;
        scr[bb] = (__log2f(red_sh[rbase] + red_sh[rbase + 1] +
                           red_sh[rbase + 2] + red_sh[rbase + 3]) + lsum) * LN2;
    }

    // ---- gold: batch bb, 128 threads each (exact f32 path) ----
    {
        const unsigned tb  = (unsigned)(b0 + bb) * S_LEN;
        const unsigned ebn = tb * T_TAG;
        float gg = 0.f;
        for (int tt = c; tt < S_LEN; tt += 128) {
            int tg = TAG_AT(tb + tt);
            bool mk = msk[bb][tt] != 0;
            if (mk) gg += emis[ebn + (unsigned)tt * T_TAG + tg];
            if (tt + 1 < S_LEN) {
                if (mk && msk[bb][tt + 1]) gg += trans[tg * T_TAG + TAG_AT(tb + tt + 1)];
            }
        }
        gg = warp_sum(gg);
        if (lane == 0) gred[wid] = gg;
    }
    __syncthreads();   // scr + gred visible

    if (tid == 0) {
        float part = (scr[0] - (gred[0] + gred[1] + gred[2] + gred[3]))
                   + (scr[1] - (gred[4] + gred[5] + gred[6] + gred[7]));
        g_partial[blockIdx.x] = part;
        __threadfence();
        int old = atomicAdd(&g_count, 1);
        is_last = (old == NCTA - 1) ? 1 : 0;
    }
    __syncthreads();

    if (is_last) {
        __threadfence();
        float vv = (tid < NCTA) ? __ldcg(&g_partial[tid]) : 0.f;
        vv = warp_sum(vv);
        if (lane == 0) gred[wid] = vv;
        __syncthreads();
        if (tid == 0) {
            float tot = 0.f;
#pragma unroll
            for (int w = 0; w < 8; w++) tot += gred[w];
            out[0] = tot * (1.0f / (float)B_TOT);
            g_count = 0;   // reset for next graph replay
        }
    }
#undef MASK_AT
#undef TAG_AT
}

extern "C" void kernel_launch(void* const* d_in, const int* in_sizes, int n_in,
                              void* d_out, int out_size) {
    const float* emis  = (const float*)d_in[0];
    const void*  tags  = d_in[1];
    const void*  mask  = d_in[2];
    const float* trans = (const float*)d_in[3];
    float* out = (float*)d_out;

    crf_main<<<NCTA, NTHREADS>>>(emis, tags, mask, trans, out);
}